// round 2
// baseline (speedup 1.0000x reference)
#include <cuda_runtime.h>
#include <stdint.h>

// Problem constants
#define NUM_FILLERS 50257
#define NUM_ROLES   512
#define D1    256
#define D2    256
#define ODIM  1024
#define BB    64
#define SS    128
#define KTOT  (D1 * D2)   // 65536

// K-split for stage-2 GEMM (deterministic partial buffer, no float atomics)
#define KSPLIT 64
#define KPER   (KTOT / KSPLIT)   // 1024
#define KC     32                // k-chunk per smem stage
#define NT     128               // o-columns per block in stage 2

// Device-global scratch (allocation-free per harness rules)
__device__ float g_tp[(size_t)BB * KTOT];                    // tp[b][k], 16.7 MB
__device__ float g_partial[(size_t)KSPLIT * BB * ODIM];      // 16.7 MB

// packed fp32x2 FMA: acc.{x,y} += a.{x,y} * w.{x,y}
__device__ __forceinline__ void fma2(unsigned long long& acc,
                                     unsigned long long a,
                                     unsigned long long w) {
    asm("fma.rn.f32x2 %0, %1, %2, %0;" : "+l"(acc) : "l"(a), "l"(w));
}

// ---------------------------------------------------------------------------
// Stage 1: tp[b, d, e] = sum_s filler_table[fillers[b,s], d] * role_table[roles[b,s], e]
// Block = (e-tile of 64, batch b). Thread tile = 8 d x 8 e (4 e-pairs).
// f is stored DUPLICATED (t,t) in smem so the inner loop is pure LDS.64+FFMA2.
// ---------------------------------------------------------------------------
__global__ __launch_bounds__(256) void tp_kernel(
    const int*   __restrict__ fillers,
    const int*   __restrict__ roles,
    const float* __restrict__ ftab,
    const float* __restrict__ rtab)
{
    const int b  = blockIdx.y;
    const int e0 = blockIdx.x * 64;
    const int tid = threadIdx.x;

    __shared__ int    s_fi[SS];
    __shared__ int    s_ri[SS];
    __shared__ float2 sF[16][D1];        // duplicated filler embeddings (32 KB)
    __shared__ float  sR[16][64];        // role embedding e-tile (4 KB)

    if (tid < SS)            s_fi[tid]      = fillers[b * SS + tid];
    else if (tid < 2 * SS)   s_ri[tid - SS] = roles[b * SS + (tid - SS)];
    __syncthreads();

    const int te  = tid & 7;     // e-pair group: e = te*2 + 16*j
    const int tdd = tid >> 3;    // d base: d = tdd + 32*i

    unsigned long long acc[8][4];
    #pragma unroll
    for (int i = 0; i < 8; i++)
        #pragma unroll
        for (int j = 0; j < 4; j++) acc[i][j] = 0ull;

    for (int sc = 0; sc < SS; sc += 16) {
        __syncthreads();
        // stage filler rows (16 s x 256 d, duplicated)
        {
            const int s_l  = tid >> 4;          // 0..15
            const int dseg = (tid & 15) * 16;   // 16 d's per thread
            const float* row = ftab + (size_t)s_fi[sc + s_l] * D1 + dseg;
            #pragma unroll
            for (int q = 0; q < 4; q++) {
                float4 v = *(const float4*)(row + q * 4);
                sF[s_l][dseg + q*4 + 0] = make_float2(v.x, v.x);
                sF[s_l][dseg + q*4 + 1] = make_float2(v.y, v.y);
                sF[s_l][dseg + q*4 + 2] = make_float2(v.z, v.z);
                sF[s_l][dseg + q*4 + 3] = make_float2(v.w, v.w);
            }
            // stage role e-tile (16 s x 64 e)
            const int e4 = (tid & 15) * 4;
            float4 rv = *(const float4*)(rtab + (size_t)s_ri[sc + s_l] * D2 + e0 + e4);
            sR[s_l][e4 + 0] = rv.x; sR[s_l][e4 + 1] = rv.y;
            sR[s_l][e4 + 2] = rv.z; sR[s_l][e4 + 3] = rv.w;
        }
        __syncthreads();

        #pragma unroll
        for (int s = 0; s < 16; s++) {
            unsigned long long a[8], w[4];
            #pragma unroll
            for (int i = 0; i < 8; i++)
                a[i] = *(const unsigned long long*)&sF[s][tdd + 32 * i];
            #pragma unroll
            for (int j = 0; j < 4; j++)
                w[j] = *(const unsigned long long*)&sR[s][te * 2 + 16 * j];
            #pragma unroll
            for (int i = 0; i < 8; i++)
                #pragma unroll
                for (int j = 0; j < 4; j++)
                    fma2(acc[i][j], a[i], w[j]);
        }
    }

    // write tp[b][d*256 + e] (8B stores, 64B-coalesced across te)
    float* tpb = g_tp + (size_t)b * KTOT;
    #pragma unroll
    for (int i = 0; i < 8; i++) {
        const int d = tdd + 32 * i;
        #pragma unroll
        for (int j = 0; j < 4; j++) {
            const int e = e0 + te * 2 + 16 * j;
            *(unsigned long long*)(tpb + (size_t)d * D2 + e) = acc[i][j];
        }
    }
}

// ---------------------------------------------------------------------------
// Stage 2: partial[ks][b][o] = sum_{k in split} tp[b,k] * W[o,k]
// Block = (o-tile of 128, k-split). Thread tile = 8 b x 4 o (2 o-pairs).
// tp stored DUPLICATED (t,t) in smem; W stored transposed [k][o].
// Inner loop: 8+2 LDS.64 + 16 FFMA2 per k -> fma-pipe bound.
// ---------------------------------------------------------------------------
__global__ __launch_bounds__(256) void gemm2_kernel(const float* __restrict__ Wm)
{
    const int o0     = blockIdx.x * NT;           // 0..896
    const int ks     = blockIdx.y;                // 0..63
    const int k_base = ks * KPER;
    const int tid    = threadIdx.x;

    __shared__ float2 sTP[KC][64 + 2];            // duplicated tp (16.9 KB)
    __shared__ float  sW[KC][NT + 4];             // W transposed  (16.9 KB)

    const int tb = tid & 7;    // b = tb + 8*i
    const int to = tid >> 3;   // o-pair = o0 + to*2 + 64*j

    unsigned long long acc[8][2];
    #pragma unroll
    for (int i = 0; i < 8; i++) { acc[i][0] = 0ull; acc[i][1] = 0ull; }

    const int k4 = (tid & 7) * 4;   // staging k offset
    const int gl = tid >> 3;        // staging row index 0..31

    for (int kc = 0; kc < KPER; kc += KC) {
        const int k0 = k_base + kc;
        __syncthreads();
        // stage W chunk: read coalesced along k (128B segments), write [k][o]
        #pragma unroll
        for (int p = 0; p < 4; p++) {
            const int o = gl + 32 * p;            // 0..127
            float4 v = *(const float4*)(Wm + (size_t)(o0 + o) * KTOT + k0 + k4);
            sW[k4 + 0][o] = v.x; sW[k4 + 1][o] = v.y;
            sW[k4 + 2][o] = v.z; sW[k4 + 3][o] = v.w;
        }
        // stage tp chunk: 32 k x 64 b, duplicated
        #pragma unroll
        for (int p = 0; p < 2; p++) {
            const int b = gl + 32 * p;            // 0..63
            float4 v = *(const float4*)(g_tp + (size_t)b * KTOT + k0 + k4);
            sTP[k4 + 0][b] = make_float2(v.x, v.x);
            sTP[k4 + 1][b] = make_float2(v.y, v.y);
            sTP[k4 + 2][b] = make_float2(v.z, v.z);
            sTP[k4 + 3][b] = make_float2(v.w, v.w);
        }
        __syncthreads();

        #pragma unroll 8
        for (int k = 0; k < KC; k++) {
            unsigned long long a[8], w[2];
            #pragma unroll
            for (int i = 0; i < 8; i++)
                a[i] = *(const unsigned long long*)&sTP[k][tb + 8 * i];
            #pragma unroll
            for (int j = 0; j < 2; j++)
                w[j] = *(const unsigned long long*)&sW[k][to * 2 + 64 * j];
            #pragma unroll
            for (int i = 0; i < 8; i++) {
                fma2(acc[i][0], a[i], w[0]);
                fma2(acc[i][1], a[i], w[1]);
            }
        }
    }

    float* part = g_partial + (size_t)ks * (BB * ODIM);
    #pragma unroll
    for (int i = 0; i < 8; i++) {
        const int b = tb + 8 * i;
        #pragma unroll
        for (int j = 0; j < 2; j++) {
            const int o = o0 + to * 2 + 64 * j;
            *(unsigned long long*)(part + (size_t)b * ODIM + o) = acc[i][j];
        }
    }
}

// ---------------------------------------------------------------------------
// Reduce: out[b][o] = bias[o] + sum_ks partial[ks][b][o]
// ---------------------------------------------------------------------------
__global__ __launch_bounds__(256) void reduce_kernel(
    const float* __restrict__ bias, float* __restrict__ out)
{
    const int idx = blockIdx.x * blockDim.x + threadIdx.x;  // 16384 threads
    const int o4 = (idx * 4) & (ODIM - 1);
    const int b  = (idx * 4) >> 10;

    float4 acc = *(const float4*)(bias + o4);
    const float* p = g_partial + (size_t)b * ODIM + o4;
    #pragma unroll 8
    for (int ks = 0; ks < KSPLIT; ks++) {
        float4 v = *(const float4*)(p + (size_t)ks * (BB * ODIM));
        acc.x += v.x; acc.y += v.y; acc.z += v.z; acc.w += v.w;
    }
    *(float4*)(out + (size_t)b * ODIM + o4) = acc;
}

// ---------------------------------------------------------------------------
extern "C" void kernel_launch(void* const* d_in, const int* in_sizes, int n_in,
                              void* d_out, int out_size)
{
    const int*   fillers = (const int*)  d_in[0];
    const int*   roles   = (const int*)  d_in[1];
    const float* ftab    = (const float*)d_in[2];
    const float* rtab    = (const float*)d_in[3];
    const float* Wm      = (const float*)d_in[4];
    const float* bias    = (const float*)d_in[5];
    float* out = (float*)d_out;

    tp_kernel   <<<dim3(D2 / 64, BB),      256>>>(fillers, roles, ftab, rtab);
    gemm2_kernel<<<dim3(ODIM / NT, KSPLIT), 256>>>(Wm);
    reduce_kernel<<<(BB * ODIM / 4) / 256, 256>>>(bias, out);
}

// round 4
// speedup vs baseline: 3.4067x; 3.4067x over previous
#include <cuda_runtime.h>
#include <stdint.h>

#define D1    256
#define D2    256
#define ODIM  1024
#define BB    64
#define SS    128
#define KTOT  (D1 * D2)       // 65536

// ---------------- stage-2 mma.sync GEMM config ----------------
#define KS2   16              // k-splits
#define NT2   128             // n-tile (output cols per CTA)
#define KC2   32              // k per pipeline stage
#define STG   6               // pipeline depth
#define PRE   5               // prefetch distance (< STG)
#define KPER2 (KTOT / KS2)    // 4096
#define NIT   (KPER2 / KC2)   // 128 stages

#define PITCH        36                          // floats per smem row (32 data + 4 pad)
#define A_FLOATS     (64  * PITCH)               // 2304
#define B_FLOATS     (NT2 * PITCH)               // 4608
#define STAGE_FLOATS (A_FLOATS + B_FLOATS)       // 6912
#define SMEM_DYN     (STG * STAGE_FLOATS * 4)    // 165888 B

// Device-global scratch (allocation-free per harness rules)
__device__ float g_tp[(size_t)BB * KTOT];                 // tp[b][k] (tf32-rounded)
__device__ float g_partial[(size_t)KS2 * BB * ODIM];      // 4 MB

// ---------------------------------------------------------------------------
// helpers
// ---------------------------------------------------------------------------
__device__ __forceinline__ uint32_t smem_u32(const void* p) {
    uint32_t a;
    asm("{ .reg .u64 t; cvta.to.shared.u64 t, %1; cvt.u32.u64 %0, t; }" : "=r"(a) : "l"(p));
    return a;
}
__device__ __forceinline__ void fma2(unsigned long long& acc,
                                     unsigned long long a, unsigned long long w) {
    asm("fma.rn.f32x2 %0, %1, %2, %0;" : "+l"(acc) : "l"(a), "l"(w));
}
__device__ __forceinline__ unsigned long long round_tf32x2(unsigned long long v) {
    float2 f = *(float2*)&v;
    uint32_t lo, hi;
    asm("cvt.rna.tf32.f32 %0, %1;" : "=r"(lo) : "f"(f.x));
    asm("cvt.rna.tf32.f32 %0, %1;" : "=r"(hi) : "f"(f.y));
    return (unsigned long long)lo | ((unsigned long long)hi << 32);
}
__device__ __forceinline__ uint32_t to_tf32(float f) {
    uint32_t r;
    asm("cvt.rna.tf32.f32 %0, %1;" : "=r"(r) : "f"(f));
    return r;
}
__device__ __forceinline__ void cp16(uint32_t dst, const void* src) {
    asm volatile("cp.async.cg.shared.global [%0], [%1], 16;" :: "r"(dst), "l"(src));
}
// m16n8k8 tf32: A row-major (4 regs), B col-major (2 regs), C fp32 (4 regs)
__device__ __forceinline__ void mma_tf32(float* c, const uint32_t* a, const uint32_t* b) {
    asm volatile(
        "mma.sync.aligned.m16n8k8.row.col.f32.tf32.tf32.f32 "
        "{%0,%1,%2,%3}, {%4,%5,%6,%7}, {%8,%9}, {%0,%1,%2,%3};"
        : "+f"(c[0]), "+f"(c[1]), "+f"(c[2]), "+f"(c[3])
        : "r"(a[0]), "r"(a[1]), "r"(a[2]), "r"(a[3]), "r"(b[0]), "r"(b[1]));
}

// ---------------------------------------------------------------------------
// Stage 1: tp[b, d, e] = sum_s F[fillers[b,s], d] * R[roles[b,s], e]
// grid (e-tiles=4, b=64, d-halves=2), 256 thr. Output rounded to tf32.
// ---------------------------------------------------------------------------
__global__ __launch_bounds__(256) void tp_kernel(
    const int*   __restrict__ fillers,
    const int*   __restrict__ roles,
    const float* __restrict__ ftab,
    const float* __restrict__ rtab)
{
    const int b   = blockIdx.y;
    const int e0  = blockIdx.x * 64;
    const int d0  = blockIdx.z * 128;
    const int tid = threadIdx.x;

    __shared__ int    s_fi[SS];
    __shared__ int    s_ri[SS];
    __shared__ float2 sF[16][128];   // duplicated filler embeddings (16 KB)
    __shared__ float  sR[16][64];    // role e-tile (4 KB)

    if (tid < SS)          s_fi[tid]      = fillers[b * SS + tid];
    else if (tid < 2 * SS) s_ri[tid - SS] = roles[b * SS + (tid - SS)];
    __syncthreads();

    const int te  = tid & 7;
    const int tdd = tid >> 3;

    unsigned long long acc[4][4];
    #pragma unroll
    for (int i = 0; i < 4; i++)
        #pragma unroll
        for (int j = 0; j < 4; j++) acc[i][j] = 0ull;

    for (int sc = 0; sc < SS; sc += 16) {
        __syncthreads();
        {
            const int s_l  = tid >> 4;
            const int dseg = (tid & 15) * 8;
            const float* row = ftab + (size_t)s_fi[sc + s_l] * D1 + d0 + dseg;
            float4 v0 = ((const float4*)row)[0];
            float4 v1 = ((const float4*)row)[1];
            sF[s_l][dseg + 0] = make_float2(v0.x, v0.x);
            sF[s_l][dseg + 1] = make_float2(v0.y, v0.y);
            sF[s_l][dseg + 2] = make_float2(v0.z, v0.z);
            sF[s_l][dseg + 3] = make_float2(v0.w, v0.w);
            sF[s_l][dseg + 4] = make_float2(v1.x, v1.x);
            sF[s_l][dseg + 5] = make_float2(v1.y, v1.y);
            sF[s_l][dseg + 6] = make_float2(v1.z, v1.z);
            sF[s_l][dseg + 7] = make_float2(v1.w, v1.w);
            const int e4 = (tid & 15) * 4;
            float4 rv = *(const float4*)(rtab + (size_t)s_ri[sc + s_l] * D2 + e0 + e4);
            sR[s_l][e4 + 0] = rv.x; sR[s_l][e4 + 1] = rv.y;
            sR[s_l][e4 + 2] = rv.z; sR[s_l][e4 + 3] = rv.w;
        }
        __syncthreads();

        #pragma unroll
        for (int s = 0; s < 16; s++) {
            unsigned long long a[4], w[4];
            #pragma unroll
            for (int i = 0; i < 4; i++)
                a[i] = *(const unsigned long long*)&sF[s][tdd + 32 * i];
            #pragma unroll
            for (int j = 0; j < 4; j++)
                w[j] = *(const unsigned long long*)&sR[s][te * 2 + 16 * j];
            #pragma unroll
            for (int i = 0; i < 4; i++)
                #pragma unroll
                for (int j = 0; j < 4; j++)
                    fma2(acc[i][j], a[i], w[j]);
        }
    }

    float* tpb = g_tp + (size_t)b * KTOT;
    #pragma unroll
    for (int i = 0; i < 4; i++) {
        const int d = d0 + tdd + 32 * i;
        #pragma unroll
        for (int j = 0; j < 4; j++) {
            const int e = e0 + te * 2 + 16 * j;
            *(unsigned long long*)(tpb + (size_t)d * D2 + e) = round_tf32x2(acc[i][j]);
        }
    }
}

// ---------------------------------------------------------------------------
// Stage 2: mma.sync tf32 GEMM.  partial[ks][b][o] = sum_{k in split} tp[b,k]*W[o,k]
// grid (8 n-tiles, 16 k-splits), 128 thr (4 warps), 1 CTA/SM.
// cp.async 6-stage pipeline -> pitch-36 smem (conflict-free fragment LDS) -> HMMA.
// Warp tile: 64m x 32n.  Per k8-step: 16 A-LDS + 8 B-LDS(+cvt) + 16 HMMA.
// ---------------------------------------------------------------------------
__global__ __launch_bounds__(128, 1) void gemm2_mma(const float* __restrict__ Wm)
{
    extern __shared__ float dsm[];

    const int tid  = threadIdx.x;
    const int wid  = tid >> 5;
    const int lane = tid & 31;
    const int o0   = blockIdx.x * NT2;
    const int ks   = blockIdx.y;
    const size_t k_base = (size_t)ks * KPER2;

    const int g = lane >> 2;       // group id 0..7
    const int t = lane & 3;        // thread-in-group
    const int n0 = wid * 32;       // warp's n offset within tile

    // staging mapping
    const int c8    = tid & 7;     // 16B chunk within 128B row payload
    const int rbase = tid >> 3;    // 0..15

    const uint32_t smem_base = smem_u32(dsm);

    float acc[4][4][4];
    #pragma unroll
    for (int i = 0; i < 4; i++)
        #pragma unroll
        for (int j = 0; j < 4; j++)
            #pragma unroll
            for (int q = 0; q < 4; q++) acc[i][j][q] = 0.f;

    // issue loads for stage j (empty commit if out of range)
    auto load_stage = [&](int j) {
        if (j < NIT) {
            const uint32_t sbase = smem_base + (uint32_t)(j % STG) * (STAGE_FLOATS * 4);
            const size_t kf = k_base + (size_t)j * KC2 + c8 * 4;
            #pragma unroll
            for (int p = 0; p < 4; p++) {            // A: tp rows 0..63
                const int row = rbase + 16 * p;
                cp16(sbase + (uint32_t)(row * PITCH + c8 * 4) * 4,
                     g_tp + (size_t)row * KTOT + kf);
            }
            #pragma unroll
            for (int p = 0; p < 8; p++) {            // B: W rows 0..127
                const int row = rbase + 16 * p;
                cp16(sbase + (uint32_t)(A_FLOATS + row * PITCH + c8 * 4) * 4,
                     Wm + (size_t)(o0 + row) * KTOT + kf);
            }
        }
        asm volatile("cp.async.commit_group;" ::: "memory");
    };

    #pragma unroll
    for (int j = 0; j < PRE; j++) load_stage(j);

    for (int it = 0; it < NIT; it++) {
        asm volatile("cp.async.wait_group 4;" ::: "memory");   // PRE-1
        __syncthreads();

        load_stage(it + PRE);

        const float* sA = dsm + (it % STG) * STAGE_FLOATS;
        const float* sB = sA + A_FLOATS;

        #pragma unroll
        for (int q = 0; q < 4; q++) {
            const int k0 = q * 8;
            uint32_t a[4][4];
            #pragma unroll
            for (int i = 0; i < 4; i++) {
                const int m = i * 16 + g;
                a[i][0] = __float_as_uint(sA[m       * PITCH + k0 + t]);
                a[i][1] = __float_as_uint(sA[(m + 8) * PITCH + k0 + t]);
                a[i][2] = __float_as_uint(sA[m       * PITCH + k0 + t + 4]);
                a[i][3] = __float_as_uint(sA[(m + 8) * PITCH + k0 + t + 4]);
            }
            uint32_t b[4][2];
            #pragma unroll
            for (int j = 0; j < 4; j++) {
                const int n = n0 + j * 8 + g;
                b[j][0] = to_tf32(sB[n * PITCH + k0 + t]);
                b[j][1] = to_tf32(sB[n * PITCH + k0 + t + 4]);
            }
            #pragma unroll
            for (int i = 0; i < 4; i++)
                #pragma unroll
                for (int j = 0; j < 4; j++)
                    mma_tf32(acc[i][j], a[i], b[j]);
        }
    }

    // epilogue: write partials.  C layout: rows i*16+g (+8), cols n0+j*8+2t (+1)
    float* part = g_partial + (size_t)ks * (BB * ODIM) ;
    #pragma unroll
    for (int i = 0; i < 4; i++) {
        const int b_row = i * 16 + g;
        #pragma unroll
        for (int j = 0; j < 4; j++) {
            const int col = o0 + n0 + j * 8 + 2 * t;
            *(float2*)(part + (size_t)b_row * ODIM + col) =
                make_float2(acc[i][j][0], acc[i][j][1]);
            *(float2*)(part + (size_t)(b_row + 8) * ODIM + col) =
                make_float2(acc[i][j][2], acc[i][j][3]);
        }
    }
}

// ---------------------------------------------------------------------------
// Reduce: out[b][o] = bias[o] + sum_ks partial[ks][b][o]
// ---------------------------------------------------------------------------
__global__ __launch_bounds__(256) void reduce_kernel(
    const float* __restrict__ bias, float* __restrict__ out)
{
    const int idx = blockIdx.x * blockDim.x + threadIdx.x;
    const int o4  = (idx * 4) & (ODIM - 1);
    const int b   = (idx * 4) >> 10;

    float4 acc = *(const float4*)(bias + o4);
    const float* p = g_partial + (size_t)b * ODIM + o4;
    #pragma unroll
    for (int ks = 0; ks < KS2; ks++) {
        float4 v = *(const float4*)(p + (size_t)ks * (BB * ODIM));
        acc.x += v.x; acc.y += v.y; acc.z += v.z; acc.w += v.w;
    }
    *(float4*)(out + (size_t)b * ODIM + o4) = acc;
}

// ---------------------------------------------------------------------------
extern "C" void kernel_launch(void* const* d_in, const int* in_sizes, int n_in,
                              void* d_out, int out_size)
{
    const int*   fillers = (const int*)  d_in[0];
    const int*   roles   = (const int*)  d_in[1];
    const float* ftab    = (const float*)d_in[2];
    const float* rtab    = (const float*)d_in[3];
    const float* Wm      = (const float*)d_in[4];
    const float* bias    = (const float*)d_in[5];
    float* out = (float*)d_out;

    cudaFuncSetAttribute(gemm2_mma, cudaFuncAttributeMaxDynamicSharedMemorySize, SMEM_DYN);

    tp_kernel    <<<dim3(D2 / 64, BB, 2), 256>>>(fillers, roles, ftab, rtab);
    gemm2_mma    <<<dim3(ODIM / NT2, KS2), 128, SMEM_DYN>>>(Wm);
    reduce_kernel<<<(BB * ODIM / 4) / 256, 256>>>(bias, out);
}